// round 8
// baseline (speedup 1.0000x reference)
#include <cuda_runtime.h>
#include <cuda_bf16.h>
#include <cstdint>

// ---------------- problem constants ----------------
#define BATCH 256
#define TT    200
#define EMBD  300
#define PD    30
#define MEM   300
#define KDEP  5
#define KP0   384     // padded K, layer-0 dense (360 -> 384)
#define KP1   320     // padded K, layer-1 dense (300 -> 320)
#define NP    320     // padded N (300 -> 320)
#define SP    224     // padded sequence (K of adjacency GEMM, 200 -> 224)

constexpr long BT = (long)BATCH * TT;   // 51200

// ---------------- scratch (device globals; zero-initialized at load) ----------------
__device__ __nv_bfloat16 g_xh[BT * KP0], g_xl[BT * KP0];             // x split [bt][384]
__device__ __nv_bfloat16 g_hh[BT * KP1], g_hl[BT * KP1];             // h split [bt][320]
__device__ __nv_bfloat16 g_yh[(long)BATCH * SP * NP], g_yl[(long)BATCH * SP * NP]; // y [b][s][n]
__device__ __nv_bfloat16 g_zh[(long)BATCH * SP * NP], g_zl[(long)BATCH * SP * NP]; // z [b][s][n]
__device__ __nv_bfloat16 g_ab[(BT + 64) * SP];                       // (A+I) bf16 [b][t][s] (+pad rows)
__device__ __nv_bfloat16 g_w0h[NP * KP0], g_w0l[NP * KP0];           // W0a^T split [320][384]
__device__ __nv_bfloat16 g_w1h[NP * KP1], g_w1l[NP * KP1];           // W1^T  split [320][320]
__device__ float g_c[BT * MEM];                                      // dep contribution
__device__ float g_rd[BT];                                           // 1/denom

// ---------------- helpers ----------------
__device__ __forceinline__ uint32_t smem_u32(const void* p) {
    return (uint32_t)__cvta_generic_to_shared(p);
}
__device__ __forceinline__ void bsplit(float v, __nv_bfloat16& h, __nv_bfloat16& l) {
    h = __float2bfloat16(v);
    l = __float2bfloat16(v - __bfloat162float(h));
}
__device__ __forceinline__ uint32_t bpack(__nv_bfloat16 a, __nv_bfloat16 b) {
    return (uint32_t)__bfloat16_as_ushort(a) | ((uint32_t)__bfloat16_as_ushort(b) << 16);
}
__device__ __forceinline__ void cp16(uint32_t dst, const void* src) {
    asm volatile("cp.async.cg.shared.global [%0], [%1], 16;" :: "r"(dst), "l"(src));
}
__device__ __forceinline__ void cp_commit() {
    asm volatile("cp.async.commit_group;" ::: "memory");
}
template <int N>
__device__ __forceinline__ void cp_wait() {
    asm volatile("cp.async.wait_group %0;" :: "n"(N) : "memory");
}
__device__ __forceinline__ void ldm_x4(uint32_t (&r)[4], uint32_t addr) {
    asm volatile("ldmatrix.sync.aligned.m8n8.x4.shared.b16 {%0,%1,%2,%3}, [%4];"
                 : "=r"(r[0]), "=r"(r[1]), "=r"(r[2]), "=r"(r[3]) : "r"(addr));
}
__device__ __forceinline__ void ldm_x4t(uint32_t (&r)[4], uint32_t addr) {
    asm volatile("ldmatrix.sync.aligned.m8n8.x4.trans.shared.b16 {%0,%1,%2,%3}, [%4];"
                 : "=r"(r[0]), "=r"(r[1]), "=r"(r[2]), "=r"(r[3]) : "r"(addr));
}
__device__ __forceinline__ void mma_bf16(float (&d)[4], const uint32_t (&a)[4],
                                         const uint32_t (&b)[2]) {
    asm volatile(
        "mma.sync.aligned.m16n8k16.row.col.f32.bf16.bf16.f32 "
        "{%0,%1,%2,%3}, {%4,%5,%6,%7}, {%8,%9}, {%0,%1,%2,%3};"
        : "+f"(d[0]), "+f"(d[1]), "+f"(d[2]), "+f"(d[3])
        : "r"(a[0]), "r"(a[1]), "r"(a[2]), "r"(a[3]), "r"(b[0]), "r"(b[1]));
}

// ---------------- K0: row/col sums of A -> 1/denom, out_mask ----------------
__global__ void k_prep(const int* __restrict__ adj, float* __restrict__ out,
                       int write_mask) {
    int b = blockIdx.x;
    const int* Ab = adj + (long)b * TT * TT;
    int t = threadIdx.x;

    __shared__ int rows[TT];
    for (int i = t; i < TT; i += blockDim.x) rows[i] = 0;
    __syncthreads();

    int cs = 0;
    for (int s = 0; s < TT; s++) {
        int v = (t < TT) ? Ab[s * TT + t] : 0;
        cs += v;
        #pragma unroll
        for (int o = 16; o > 0; o >>= 1) v += __shfl_down_sync(0xffffffff, v, o);
        if ((threadIdx.x & 31) == 0) atomicAdd(&rows[s], v);
    }
    __syncthreads();

    if (t < TT) {
        int rs = rows[t];
        g_rd[b * TT + t] = 1.0f / (float)(rs + 1);
        if (write_mask)
            out[BT * MEM + (long)b * TT + t] = (rs + cs == 0) ? 1.0f : 0.0f;
    }
}

// ---------------- K0b: adjacency + I -> bf16, [b][t][224] ----------------
__global__ void k_adjconv(const int* __restrict__ adj) {
    long idx = (long)blockIdx.x * 256 + threadIdx.x;     // one int4 (4 cols) each
    int s4 = (int)(idx % (TT / 4)) * 4;
    long bt = idx / (TT / 4);
    int t = (int)(bt % TT);
    int4 v = *(const int4*)(adj + bt * TT + s4);
    float f0 = (float)v.x, f1 = (float)v.y, f2 = (float)v.z, f3 = (float)v.w;
    int dd = t - s4;
    if (dd >= 0 && dd < 4) {
        if (dd == 0) f0 += 1.0f; else if (dd == 1) f1 += 1.0f;
        else if (dd == 2) f2 += 1.0f; else f3 += 1.0f;
    }
    uint2 p;
    p.x = bpack(__float2bfloat16(f0), __float2bfloat16(f1));
    p.y = bpack(__float2bfloat16(f2), __float2bfloat16(f3));
    *(uint2*)&g_ab[bt * SP + s4] = p;
}

// ---------------- K1: embedding gather (split bf16) + dep vector c ----------------
__global__ void k_embed(const int* __restrict__ words, const int* __restrict__ pos,
                        const int* __restrict__ ner, const int* __restrict__ dep_ids,
                        const int* __restrict__ dep_mask,
                        const float* __restrict__ wemb, const float* __restrict__ pemb,
                        const float* __restrict__ nemb, const float* __restrict__ demb,
                        const float* __restrict__ W0w, const float* __restrict__ W0b) {
    long bt = blockIdx.x;
    int tid = threadIdx.x;
    __shared__ float sg[PD];

    float v = 0.0f;
    bool have = false;
    if (tid < EMBD) { v = wemb[(long)words[bt] * EMBD + tid]; have = true; }
    else if (tid < EMBD + PD) { v = pemb[pos[bt] * PD + (tid - EMBD)]; have = true; }
    else if (tid < EMBD + 2 * PD) { v = nemb[ner[bt] * PD + (tid - EMBD - PD)]; have = true; }
    if (have) {
        __nv_bfloat16 h, l; bsplit(v, h, l);
        g_xh[bt * KP0 + tid] = h;
        g_xl[bt * KP0 + tid] = l;
    }

    if (tid < PD) {
        float s = 0.0f;
        int any = 0;
        #pragma unroll
        for (int j = 0; j < KDEP; j++) {
            int m  = dep_mask[bt * KDEP + j];
            int id = dep_ids[bt * KDEP + j];
            any += m;
            s += m ? demb[id * PD + tid] : 0.0f;
        }
        if (any == 0) s = demb[tid];
        sg[tid] = s + demb[PD + tid];
    }
    __syncthreads();

    if (tid < MEM) {
        const float* Wd = W0w + (long)(EMBD + 2 * PD) * MEM;   // rows 360..389
        float acc = 2.0f * W0b[tid];
        #pragma unroll
        for (int k = 0; k < PD; k++) acc += sg[k] * Wd[k * MEM + tid];
        g_c[bt * MEM + tid] = acc;
    }
}

// ---------------- K1b: transpose + split + pad the weight matrices ----------------
__global__ void k_wsplit(const float* __restrict__ W0, const float* __restrict__ W1) {
    int idx = blockIdx.x * 256 + threadIdx.x;
    if (idx < NP * KP0) {
        int n = idx / KP0, k = idx % KP0;
        float v = (n < MEM && k < EMBD + 2 * PD) ? W0[(long)k * MEM + n] : 0.0f;
        __nv_bfloat16 h, l; bsplit(v, h, l);
        g_w0h[idx] = h; g_w0l[idx] = l;
    }
    if (idx < NP * KP1) {
        int n = idx / KP1, k = idx % KP1;
        float v = (n < MEM && k < MEM) ? W1[(long)k * MEM + n] : 0.0f;
        __nv_bfloat16 h, l; bsplit(v, h, l);
        g_w1h[idx] = h; g_w1l[idx] = l;
    }
}

// ---------------- dense GEMM: y[b][s][n] = (x @ W^T), cp.async double-buffered ----------------
// CTA 128x64, 4 warps (2m x 2n), warp tile 64x32, BK=32, 3-product split bf16.
template <int KPAD>
__global__ __launch_bounds__(128)
void k_dense(const __nv_bfloat16* __restrict__ Ah, const __nv_bfloat16* __restrict__ Al,
             const __nv_bfloat16* __restrict__ Wh, const __nv_bfloat16* __restrict__ Wl,
             __nv_bfloat16* __restrict__ Yh, __nv_bfloat16* __restrict__ Yl) {
    extern __shared__ __nv_bfloat16 dsm[];
    const int OAh = 0, OAl = 5120, OBh = 10240, OBl = 12800, BUFE = 15360; // elem offsets

    int tid = threadIdx.x, lane = tid & 31, wid = tid >> 5;
    int wm = wid >> 1, wn = wid & 1;
    long m0 = (long)blockIdx.y * 128;
    int  n0 = blockIdx.x * 64;

    // pad-column trim: n-tile 4 (n0=256) wn=1 covers n 288..319; only 288..303 real
    const int ni_cnt = (n0 == 256 && wn == 1) ? 2 : 4;

    const int NCH = KPAD / 32;

    auto stage = [&](int ch, int buf) {
        int k0 = ch * 32;
        __nv_bfloat16* base = dsm + buf * BUFE;
        #pragma unroll
        for (int i = 0; i < 4; i++) {
            int idx = tid + i * 128;
            int r = idx >> 2, g = idx & 3;
            cp16(smem_u32(base + OAh + r * 40 + g * 8), Ah + (m0 + r) * KPAD + k0 + g * 8);
            cp16(smem_u32(base + OAl + r * 40 + g * 8), Al + (m0 + r) * KPAD + k0 + g * 8);
        }
        #pragma unroll
        for (int i = 0; i < 2; i++) {
            int idx = tid + i * 128;
            int r = idx >> 2, g = idx & 3;
            if (n0 == 256 && r >= 48) continue;     // cols 304..319 never consumed
            cp16(smem_u32(base + OBh + r * 40 + g * 8), Wh + (long)(n0 + r) * KPAD + k0 + g * 8);
            cp16(smem_u32(base + OBl + r * 40 + g * 8), Wl + (long)(n0 + r) * KPAD + k0 + g * 8);
        }
        cp_commit();
    };

    float acc[4][4][4];
    #pragma unroll
    for (int i = 0; i < 4; i++)
        #pragma unroll
        for (int j = 0; j < 4; j++)
            #pragma unroll
            for (int q = 0; q < 4; q++) acc[i][j][q] = 0.0f;

    stage(0, 0);
    for (int ch = 0; ch < NCH; ch++) {
        int buf = ch & 1;
        if (ch + 1 < NCH) { stage(ch + 1, buf ^ 1); cp_wait<1>(); }
        else              { cp_wait<0>(); }
        __syncthreads();

        uint32_t uAh = smem_u32(dsm + buf * BUFE + OAh);
        uint32_t uAl = smem_u32(dsm + buf * BUFE + OAl);
        uint32_t uBh = smem_u32(dsm + buf * BUFE + OBh);
        uint32_t uBl = smem_u32(dsm + buf * BUFE + OBl);

        #pragma unroll
        for (int ks = 0; ks < 32; ks += 16) {
            uint32_t ah[4][4], al[4][4], bh[4][2], bl[4][2];
            #pragma unroll
            for (int mi = 0; mi < 4; mi++) {
                uint32_t off = (uint32_t)(((wm * 64 + mi * 16 + (lane & 15)) * 40 +
                                           ks + ((lane >> 4) << 3)) * 2);
                ldm_x4(ah[mi], uAh + off);
                ldm_x4(al[mi], uAl + off);
            }
            // B fragments: x4 loads two n8-frags at once
            #pragma unroll
            for (int p = 0; p < 2; p++) {
                if (p * 2 >= ni_cnt) break;
                uint32_t off = (uint32_t)(((wn * 32 + p * 16 + (lane & 7) + ((lane >> 4) << 3)) * 40 +
                                           ks + (((lane >> 3) & 1) << 3)) * 2);
                uint32_t r4[4];
                ldm_x4(r4, uBh + off);
                bh[p * 2][0] = r4[0]; bh[p * 2][1] = r4[1];
                bh[p * 2 + 1][0] = r4[2]; bh[p * 2 + 1][1] = r4[3];
                ldm_x4(r4, uBl + off);
                bl[p * 2][0] = r4[0]; bl[p * 2][1] = r4[1];
                bl[p * 2 + 1][0] = r4[2]; bl[p * 2 + 1][1] = r4[3];
            }
            #pragma unroll
            for (int mi = 0; mi < 4; mi++)
                #pragma unroll 4
                for (int ni = 0; ni < ni_cnt; ni++) {
                    mma_bf16(acc[mi][ni], ah[mi], bh[ni]);
                    mma_bf16(acc[mi][ni], ah[mi], bl[ni]);
                    mma_bf16(acc[mi][ni], al[mi], bh[ni]);
                }
        }
        __syncthreads();
    }

    // epilogue: write y split bf16, natural [b][s][n]; skipped pad cols stay zero-init
    #pragma unroll
    for (int mi = 0; mi < 4; mi++) {
        #pragma unroll
        for (int half = 0; half < 2; half++) {
            long row = m0 + wm * 64 + mi * 16 + (lane >> 2) + half * 8;
            long b = row / TT;
            int  s = (int)(row % TT);
            long base = (b * SP + s) * NP;
            #pragma unroll 4
            for (int ni = 0; ni < ni_cnt; ni++) {
                int n = n0 + wn * 32 + ni * 8 + (lane & 3) * 2;
                float v0 = acc[mi][ni][half * 2 + 0];
                float v1 = acc[mi][ni][half * 2 + 1];
                __nv_bfloat16 h0, l0, h1, l1;
                bsplit(v0, h0, l0); bsplit(v1, h1, l1);
                *(uint32_t*)&Yh[base + n] = bpack(h0, h1);
                *(uint32_t*)&Yl[base + n] = bpack(l0, l1);
            }
        }
    }
}

// ---------------- adjacency GEMM: D = (A+I) @ y, cp.async double-buffered ----------------
// m-tiles {0,128}: no overlap; second tile trims mi per warp (rows 200..255 skipped).
__global__ __launch_bounds__(128)
void k_adj(const __nv_bfloat16* __restrict__ Yh, const __nv_bfloat16* __restrict__ Yl,
           const float* __restrict__ cvec, const float* __restrict__ bias,
           __nv_bfloat16* __restrict__ Hh, __nv_bfloat16* __restrict__ Hl,
           float* __restrict__ outp, int layer0) {
    __shared__ __nv_bfloat16 sA[2][128 * 40];
    __shared__ __nv_bfloat16 sYh[2][32 * 72], sYl[2][32 * 72];

    int tid = threadIdx.x, lane = tid & 31, wid = tid >> 5;
    int wm = wid >> 1, wn = wid & 1;
    int b  = blockIdx.z;
    int m0 = blockIdx.y * 128;      // 0 or 128
    int n0 = blockIdx.x * 64;

    const int mi_cnt = (m0 == 0 || wm == 0) ? 4 : 1;             // tile2 wm1: rows 192..207 only
    const int ni_cnt = (n0 == 256 && wn == 1) ? 2 : 4;           // pad-col trim

    auto stage = [&](int ch, int buf) {
        int k0 = ch * 32;
        #pragma unroll
        for (int i = 0; i < 4; i++) {
            int idx = tid + i * 128;
            int r = idx >> 2, g = idx & 3;
            if (m0 != 0 && r >= 80) continue;       // rows 208..255 never consumed
            cp16(smem_u32(&sA[buf][r * 40 + g * 8]),
                 &g_ab[((long)b * TT + m0 + r) * SP + k0 + g * 8]);
        }
        #pragma unroll
        for (int i = 0; i < 2; i++) {
            int idx = tid + i * 128;
            int r = idx >> 3, g = idx & 7;
            long gb = ((long)b * SP + k0 + r) * NP + n0 + g * 8;
            cp16(smem_u32(&sYh[buf][r * 72 + g * 8]), &Yh[gb]);
            cp16(smem_u32(&sYl[buf][r * 72 + g * 8]), &Yl[gb]);
        }
        cp_commit();
    };

    float acc[4][4][4];
    #pragma unroll
    for (int i = 0; i < 4; i++)
        #pragma unroll
        for (int j = 0; j < 4; j++)
            #pragma unroll
            for (int q = 0; q < 4; q++) acc[i][j][q] = 0.0f;

    const int NCH = SP / 32;   // 7
    stage(0, 0);
    for (int ch = 0; ch < NCH; ch++) {
        int buf = ch & 1;
        if (ch + 1 < NCH) { stage(ch + 1, buf ^ 1); cp_wait<1>(); }
        else              { cp_wait<0>(); }
        __syncthreads();

        uint32_t uA  = smem_u32(sA[buf]);
        uint32_t uYh = smem_u32(sYh[buf]);
        uint32_t uYl = smem_u32(sYl[buf]);

        #pragma unroll
        for (int ks = 0; ks < 32; ks += 16) {
            uint32_t aa[4][4], bh[4][2], bl[4][2];
            #pragma unroll 4
            for (int mi = 0; mi < mi_cnt; mi++) {
                uint32_t off = (uint32_t)(((wm * 64 + mi * 16 + (lane & 15)) * 40 +
                                           ks + ((lane >> 4) << 3)) * 2);
                ldm_x4(aa[mi], uA + off);
            }
            #pragma unroll
            for (int p = 0; p < 2; p++) {
                if (p * 2 >= ni_cnt) break;
                uint32_t off = (uint32_t)(((ks + (lane & 15)) * 72 +
                                           wn * 32 + p * 16 + ((lane >> 4) << 3)) * 2);
                uint32_t r4[4];
                ldm_x4t(r4, uYh + off);
                bh[p * 2][0] = r4[0]; bh[p * 2][1] = r4[1];
                bh[p * 2 + 1][0] = r4[2]; bh[p * 2 + 1][1] = r4[3];
                ldm_x4t(r4, uYl + off);
                bl[p * 2][0] = r4[0]; bl[p * 2][1] = r4[1];
                bl[p * 2 + 1][0] = r4[2]; bl[p * 2 + 1][1] = r4[3];
            }
            #pragma unroll 4
            for (int mi = 0; mi < mi_cnt; mi++)
                #pragma unroll 4
                for (int ni = 0; ni < ni_cnt; ni++) {
                    mma_bf16(acc[mi][ni], aa[mi], bh[ni]);
                    mma_bf16(acc[mi][ni], aa[mi], bl[ni]);
                }
        }
        __syncthreads();
    }

    // fused epilogue
    #pragma unroll 4
    for (int mi = 0; mi < mi_cnt; mi++) {
        #pragma unroll
        for (int half = 0; half < 2; half++) {
            int t = m0 + wm * 64 + mi * 16 + (lane >> 2) + half * 8;
            if (t >= TT) continue;
            long bt = (long)b * TT + t;
            float rd = g_rd[bt];
            #pragma unroll 4
            for (int ni = 0; ni < ni_cnt; ni++) {
                int n = n0 + wn * 32 + ni * 8 + (lane & 3) * 2;
                if (n >= MEM) continue;
                float a0, a1;
                if (layer0) { a0 = cvec[bt * MEM + n]; a1 = cvec[bt * MEM + n + 1]; }
                else        { a0 = 2.0f * bias[n];     a1 = 2.0f * bias[n + 1]; }
                float v0 = (acc[mi][ni][half * 2 + 0] + a0) * rd;
                float v1 = (acc[mi][ni][half * 2 + 1] + a1) * rd;
                v0 = v0 > 0.0f ? v0 : 0.0f;
                v1 = v1 > 0.0f ? v1 : 0.0f;
                if (layer0) {
                    __nv_bfloat16 h0, l0, h1, l1;
                    bsplit(v0, h0, l0); bsplit(v1, h1, l1);
                    *(uint32_t*)&Hh[bt * KP1 + n] = bpack(h0, h1);
                    *(uint32_t*)&Hl[bt * KP1 + n] = bpack(l0, l1);
                } else {
                    *(float2*)&outp[bt * MEM + n] = make_float2(v0, v1);
                }
            }
        }
    }
}

// ---------------- launch ----------------
extern "C" void kernel_launch(void* const* d_in, const int* in_sizes, int n_in,
                              void* d_out, int out_size) {
    const int*   adj      = (const int*)d_in[0];
    const int*   words    = (const int*)d_in[1];
    const int*   pos      = (const int*)d_in[2];
    const int*   ner      = (const int*)d_in[3];
    const int*   dep_ids  = (const int*)d_in[4];
    const int*   dep_mask = (const int*)d_in[5];
    const float* wemb = (const float*)d_in[7];
    const float* pemb = (const float*)d_in[8];
    const float* nemb = (const float*)d_in[9];
    const float* demb = (const float*)d_in[10];
    const float* W0w  = (const float*)d_in[11];
    const float* W0b  = (const float*)d_in[12];
    const float* W1w  = (const float*)d_in[13];
    const float* W1b  = (const float*)d_in[14];
    float* out = (float*)d_out;

    const int SMEM_DENSE = 2 * 15360 * 2;   // 61440 bytes
    cudaFuncSetAttribute(k_dense<KP0>, cudaFuncAttributeMaxDynamicSharedMemorySize, SMEM_DENSE);
    cudaFuncSetAttribute(k_dense<KP1>, cudaFuncAttributeMaxDynamicSharedMemorySize, SMEM_DENSE);

    __nv_bfloat16 *xh, *xl, *hh, *hl, *yh, *yl, *zh, *zl, *w0h, *w0l, *w1h, *w1l;
    float* pc;
    cudaGetSymbolAddress((void**)&xh,  g_xh);  cudaGetSymbolAddress((void**)&xl,  g_xl);
    cudaGetSymbolAddress((void**)&hh,  g_hh);  cudaGetSymbolAddress((void**)&hl,  g_hl);
    cudaGetSymbolAddress((void**)&yh,  g_yh);  cudaGetSymbolAddress((void**)&yl,  g_yl);
    cudaGetSymbolAddress((void**)&zh,  g_zh);  cudaGetSymbolAddress((void**)&zl,  g_zl);
    cudaGetSymbolAddress((void**)&w0h, g_w0h); cudaGetSymbolAddress((void**)&w0l, g_w0l);
    cudaGetSymbolAddress((void**)&w1h, g_w1h); cudaGetSymbolAddress((void**)&w1l, g_w1l);
    cudaGetSymbolAddress((void**)&pc,  g_c);

    int write_mask = (out_size >= (int)(BT * MEM + BT));

    // prep (wsplit first so the ncu -s window lands on a GEMM launch)
    k_wsplit<<<(NP * KP0 + 255) / 256, 256>>>(W0w, W1w);
    k_prep<<<BATCH, 256>>>(adj, out, write_mask);
    k_adjconv<<<(int)((long)BATCH * TT * (TT / 4) / 256), 256>>>(adj);
    k_embed<<<(int)BT, 384>>>(words, pos, ner, dep_ids, dep_mask,
                              wemb, pemb, nemb, demb, W0w, W0b);

    dim3 gd(NP / 64, (int)(BT / 128));         // (5, 400)
    dim3 ga(NP / 64, 2, BATCH);                // (5, 2, 256)

    // layer 0
    k_dense<KP0><<<gd, 128, SMEM_DENSE>>>(xh, xl, w0h, w0l, yh, yl);
    k_adj<<<ga, 128>>>(yh, yl, pc, nullptr, hh, hl, nullptr, 1);

    // layer 1
    k_dense<KP1><<<gd, 128, SMEM_DENSE>>>(hh, hl, w1h, w1l, zh, zl);
    k_adj<<<ga, 128>>>(zh, zl, nullptr, W1b, nullptr, nullptr, out, 0);
}

// round 10
// speedup vs baseline: 3.3432x; 3.3432x over previous
#include <cuda_runtime.h>
#include <cuda_bf16.h>
#include <cstdint>

// ---------------- problem constants ----------------
#define BATCH 256
#define TT    200
#define EMBD  300
#define PD    30
#define MEM   300
#define KDEP  5
#define KP0   384     // padded K, layer-0 dense (360 -> 384)
#define KP1   320     // padded K, layer-1 dense (300 -> 320)
#define NP    320     // padded N (300 -> 320)
#define SP    224     // padded sequence (K of adjacency GEMM, 200 -> 224)
#define KPD   32      // padded K for dep GEMM (30 -> 32)

constexpr long BT = (long)BATCH * TT;   // 51200

// ---------------- scratch (device globals; zero-initialized at load) ----------------
__device__ __nv_bfloat16 g_xh[BT * KP0], g_xl[BT * KP0];             // x split [bt][384]
__device__ __nv_bfloat16 g_hh[BT * KP1], g_hl[BT * KP1];             // h split [bt][320]
__device__ __nv_bfloat16 g_yh[(long)BATCH * SP * NP], g_yl[(long)BATCH * SP * NP]; // y [b][s][n]
__device__ __nv_bfloat16 g_zh[(long)BATCH * SP * NP], g_zl[(long)BATCH * SP * NP]; // z [b][s][n]
__device__ __nv_bfloat16 g_ab[BT * SP];                              // (A+I) bf16 [b][t][s]
__device__ __nv_bfloat16 g_w0h[NP * KP0], g_w0l[NP * KP0];           // W0a^T split [320][384]
__device__ __nv_bfloat16 g_w1h[NP * KP1], g_w1l[NP * KP1];           // W1^T  split [320][320]
__device__ __nv_bfloat16 g_wdh[NP * KPD], g_wdl[NP * KPD];           // W0d^T split [320][32]
__device__ __nv_bfloat16 g_dvh[BT * KPD], g_dvl[BT * KPD];           // depvec split [bt][32]
__device__ float g_c[BT * MEM];                                      // dep contribution (+2*b0)
__device__ float g_rd[BT];                                           // 1/denom

// ---------------- helpers ----------------
__device__ __forceinline__ uint32_t smem_u32(const void* p) {
    return (uint32_t)__cvta_generic_to_shared(p);
}
__device__ __forceinline__ void bsplit(float v, __nv_bfloat16& h, __nv_bfloat16& l) {
    h = __float2bfloat16(v);
    l = __float2bfloat16(v - __bfloat162float(h));
}
__device__ __forceinline__ uint32_t bpack(__nv_bfloat16 a, __nv_bfloat16 b) {
    return (uint32_t)__bfloat16_as_ushort(a) | ((uint32_t)__bfloat16_as_ushort(b) << 16);
}
__device__ __forceinline__ void cp16(uint32_t dst, const void* src) {
    asm volatile("cp.async.cg.shared.global [%0], [%1], 16;" :: "r"(dst), "l"(src));
}
__device__ __forceinline__ void cp_commit() {
    asm volatile("cp.async.commit_group;" ::: "memory");
}
template <int N>
__device__ __forceinline__ void cp_wait() {
    asm volatile("cp.async.wait_group %0;" :: "n"(N) : "memory");
}
__device__ __forceinline__ void ldm_x4(uint32_t (&r)[4], uint32_t addr) {
    asm volatile("ldmatrix.sync.aligned.m8n8.x4.shared.b16 {%0,%1,%2,%3}, [%4];"
                 : "=r"(r[0]), "=r"(r[1]), "=r"(r[2]), "=r"(r[3]) : "r"(addr));
}
__device__ __forceinline__ void ldm_x4t(uint32_t (&r)[4], uint32_t addr) {
    asm volatile("ldmatrix.sync.aligned.m8n8.x4.trans.shared.b16 {%0,%1,%2,%3}, [%4];"
                 : "=r"(r[0]), "=r"(r[1]), "=r"(r[2]), "=r"(r[3]) : "r"(addr));
}
__device__ __forceinline__ void mma_bf16(float (&d)[4], const uint32_t (&a)[4],
                                         const uint32_t (&b)[2]) {
    asm volatile(
        "mma.sync.aligned.m16n8k16.row.col.f32.bf16.bf16.f32 "
        "{%0,%1,%2,%3}, {%4,%5,%6,%7}, {%8,%9}, {%0,%1,%2,%3};"
        : "+f"(d[0]), "+f"(d[1]), "+f"(d[2]), "+f"(d[3])
        : "r"(a[0]), "r"(a[1]), "r"(a[2]), "r"(a[3]), "r"(b[0]), "r"(b[1]));
}

// ---------------- K0: row/col sums of A -> 1/denom, out_mask ----------------
__global__ void k_prep(const int* __restrict__ adj, float* __restrict__ out,
                       int write_mask) {
    int b = blockIdx.x;
    const int* Ab = adj + (long)b * TT * TT;
    int t = threadIdx.x;

    __shared__ int rows[TT];
    for (int i = t; i < TT; i += blockDim.x) rows[i] = 0;
    __syncthreads();

    int cs = 0;
    for (int s = 0; s < TT; s++) {
        int v = (t < TT) ? Ab[s * TT + t] : 0;
        cs += v;
        #pragma unroll
        for (int o = 16; o > 0; o >>= 1) v += __shfl_down_sync(0xffffffff, v, o);
        if ((threadIdx.x & 31) == 0) atomicAdd(&rows[s], v);
    }
    __syncthreads();

    if (t < TT) {
        int rs = rows[t];
        g_rd[b * TT + t] = 1.0f / (float)(rs + 1);
        if (write_mask)
            out[BT * MEM + (long)b * TT + t] = (rs + cs == 0) ? 1.0f : 0.0f;
    }
}

// ---------------- K0b: adjacency + I -> bf16, [b][t][224] ----------------
__global__ void k_adjconv(const int* __restrict__ adj) {
    long idx = (long)blockIdx.x * 256 + threadIdx.x;     // one int4 (4 cols) each
    int s4 = (int)(idx % (TT / 4)) * 4;
    long bt = idx / (TT / 4);
    int t = (int)(bt % TT);
    int4 v = *(const int4*)(adj + bt * TT + s4);
    float f0 = (float)v.x, f1 = (float)v.y, f2 = (float)v.z, f3 = (float)v.w;
    int dd = t - s4;
    if (dd >= 0 && dd < 4) {
        if (dd == 0) f0 += 1.0f; else if (dd == 1) f1 += 1.0f;
        else if (dd == 2) f2 += 1.0f; else f3 += 1.0f;
    }
    uint2 p;
    p.x = bpack(__float2bfloat16(f0), __float2bfloat16(f1));
    p.y = bpack(__float2bfloat16(f2), __float2bfloat16(f3));
    *(uint2*)&g_ab[bt * SP + s4] = p;
}

// ---------------- K1a: word-embedding gather, grid-stride float4 ----------------
__global__ void k_gw(const int* __restrict__ words, const float* __restrict__ wemb) {
    long i = (long)blockIdx.x * 256 + threadIdx.x;
    if (i >= BT * 75L) return;
    long bt = i / 75;
    int  c  = (int)(i % 75);
    int  w  = words[bt];
    float4 v = *(const float4*)&wemb[(long)w * EMBD + c * 4];
    __nv_bfloat16 h0, l0, h1, l1, h2, l2, h3, l3;
    bsplit(v.x, h0, l0); bsplit(v.y, h1, l1);
    bsplit(v.z, h2, l2); bsplit(v.w, h3, l3);
    *(uint2*)&g_xh[bt * KP0 + c * 4] = make_uint2(bpack(h0, h1), bpack(h2, h3));
    *(uint2*)&g_xl[bt * KP0 + c * 4] = make_uint2(bpack(l0, l1), bpack(l2, l3));
}

// ---------------- K1b: pos/ner gather + dep vector, warp per token ----------------
__global__ void k_gpn(const int* __restrict__ pos, const int* __restrict__ ner,
                      const int* __restrict__ dep_ids, const int* __restrict__ dep_mask,
                      const float* __restrict__ pemb, const float* __restrict__ nemb,
                      const float* __restrict__ demb) {
    long bt = (long)blockIdx.x * 8 + (threadIdx.x >> 5);
    int  l  = threadIdx.x & 31;
    if (bt >= BT || l >= PD) return;

    __nv_bfloat16 h, lo;
    float pv = pemb[pos[bt] * PD + l];
    bsplit(pv, h, lo);
    g_xh[bt * KP0 + EMBD + l] = h;
    g_xl[bt * KP0 + EMBD + l] = lo;

    float nv = nemb[ner[bt] * PD + l];
    bsplit(nv, h, lo);
    g_xh[bt * KP0 + EMBD + PD + l] = h;
    g_xl[bt * KP0 + EMBD + PD + l] = lo;

    float s = 0.0f;
    int any = 0;
    #pragma unroll
    for (int j = 0; j < KDEP; j++) {
        int m  = dep_mask[bt * KDEP + j];
        int id = dep_ids[bt * KDEP + j];
        any += m;
        s += m ? demb[id * PD + l] : 0.0f;
    }
    if (any == 0) s = demb[l];          // dep_emb[0]
    s += demb[PD + l];                  // + dep_emb[SELF_LOOP=1]
    bsplit(s, h, lo);
    g_dvh[bt * KPD + l] = h;
    g_dvl[bt * KPD + l] = lo;
}

// ---------------- K1c: transpose + split + pad the weight matrices ----------------
__global__ void k_wsplit(const float* __restrict__ W0, const float* __restrict__ W1) {
    int idx = blockIdx.x * 256 + threadIdx.x;
    if (idx < NP * KP0) {
        int n = idx / KP0, k = idx % KP0;
        float v = (n < MEM && k < EMBD + 2 * PD) ? W0[(long)k * MEM + n] : 0.0f;
        __nv_bfloat16 h, l; bsplit(v, h, l);
        g_w0h[idx] = h; g_w0l[idx] = l;
    }
    if (idx < NP * KP1) {
        int n = idx / KP1, k = idx % KP1;
        float v = (n < MEM && k < MEM) ? W1[(long)k * MEM + n] : 0.0f;
        __nv_bfloat16 h, l; bsplit(v, h, l);
        g_w1h[idx] = h; g_w1l[idx] = l;
    }
    if (idx < NP * KPD) {
        int n = idx / KPD, k = idx % KPD;
        float v = (n < MEM && k < PD) ? W0[(long)(EMBD + 2 * PD + k) * MEM + n] : 0.0f;
        __nv_bfloat16 h, l; bsplit(v, h, l);
        g_wdh[idx] = h; g_wdl[idx] = l;
    }
}

// ---------------- K1d: c = dv @ Wd^T + 2*b0, tensor-core GEMM (K=32) ----------------
__global__ __launch_bounds__(128)
void k_densec(const float* __restrict__ W0b) {
    __shared__ __nv_bfloat16 sAh[128 * 40], sAl[128 * 40];
    __shared__ __nv_bfloat16 sBh[64 * 40],  sBl[64 * 40];

    int tid = threadIdx.x, lane = tid & 31, wid = tid >> 5;
    int wm = wid >> 1, wn = wid & 1;
    long m0 = (long)blockIdx.y * 128;
    int  n0 = blockIdx.x * 64;

    #pragma unroll
    for (int i = 0; i < 4; i++) {
        int idx = tid + i * 128;
        int r = idx >> 2, g = idx & 3;
        cp16(smem_u32(sAh + r * 40 + g * 8), g_dvh + (m0 + r) * KPD + g * 8);
        cp16(smem_u32(sAl + r * 40 + g * 8), g_dvl + (m0 + r) * KPD + g * 8);
    }
    #pragma unroll
    for (int i = 0; i < 2; i++) {
        int idx = tid + i * 128;
        int r = idx >> 2, g = idx & 3;
        cp16(smem_u32(sBh + r * 40 + g * 8), g_wdh + (long)(n0 + r) * KPD + g * 8);
        cp16(smem_u32(sBl + r * 40 + g * 8), g_wdl + (long)(n0 + r) * KPD + g * 8);
    }
    cp_commit();
    cp_wait<0>();
    __syncthreads();

    uint32_t uAh = smem_u32(sAh), uAl = smem_u32(sAl);
    uint32_t uBh = smem_u32(sBh), uBl = smem_u32(sBl);

    float acc[4][4][4];
    #pragma unroll
    for (int i = 0; i < 4; i++)
        #pragma unroll
        for (int j = 0; j < 4; j++)
            #pragma unroll
            for (int q = 0; q < 4; q++) acc[i][j][q] = 0.0f;

    #pragma unroll
    for (int ks = 0; ks < 32; ks += 16) {
        uint32_t ah[4][4], al[4][4], bh[4][2], bl[4][2];
        #pragma unroll
        for (int mi = 0; mi < 4; mi++) {
            uint32_t off = (uint32_t)(((wm * 64 + mi * 16 + (lane & 15)) * 40 +
                                       ks + ((lane >> 4) << 3)) * 2);
            ldm_x4(ah[mi], uAh + off);
            ldm_x4(al[mi], uAl + off);
        }
        #pragma unroll
        for (int p = 0; p < 2; p++) {
            uint32_t off = (uint32_t)(((wn * 32 + p * 16 + (lane & 7) + ((lane >> 4) << 3)) * 40 +
                                       ks + (((lane >> 3) & 1) << 3)) * 2);
            uint32_t r4[4];
            ldm_x4(r4, uBh + off);
            bh[p * 2][0] = r4[0]; bh[p * 2][1] = r4[1];
            bh[p * 2 + 1][0] = r4[2]; bh[p * 2 + 1][1] = r4[3];
            ldm_x4(r4, uBl + off);
            bl[p * 2][0] = r4[0]; bl[p * 2][1] = r4[1];
            bl[p * 2 + 1][0] = r4[2]; bl[p * 2 + 1][1] = r4[3];
        }
        #pragma unroll
        for (int mi = 0; mi < 4; mi++)
            #pragma unroll
            for (int ni = 0; ni < 4; ni++) {
                mma_bf16(acc[mi][ni], ah[mi], bh[ni]);
                mma_bf16(acc[mi][ni], ah[mi], bl[ni]);
                mma_bf16(acc[mi][ni], al[mi], bh[ni]);
            }
    }

    #pragma unroll
    for (int mi = 0; mi < 4; mi++) {
        #pragma unroll
        for (int half = 0; half < 2; half++) {
            long row = m0 + wm * 64 + mi * 16 + (lane >> 2) + half * 8;
            #pragma unroll
            for (int ni = 0; ni < 4; ni++) {
                int n = n0 + wn * 32 + ni * 8 + (lane & 3) * 2;
                if (n >= MEM) continue;
                float v0 = acc[mi][ni][half * 2 + 0] + 2.0f * W0b[n];
                float v1 = acc[mi][ni][half * 2 + 1] + 2.0f * W0b[n + 1];
                *(float2*)&g_c[row * MEM + n] = make_float2(v0, v1);
            }
        }
    }
}

// ---------------- dense GEMM: y[b][s][n] = (x @ W^T), cp.async double-buffered ----------------
// CTA 128x64, 4 warps (2m x 2n), warp tile 64x32, BK=32, 3-product split bf16.
template <int KPAD>
__global__ __launch_bounds__(128)
void k_dense(const __nv_bfloat16* __restrict__ Ah, const __nv_bfloat16* __restrict__ Al,
             const __nv_bfloat16* __restrict__ Wh, const __nv_bfloat16* __restrict__ Wl,
             __nv_bfloat16* __restrict__ Yh, __nv_bfloat16* __restrict__ Yl) {
    extern __shared__ __nv_bfloat16 dsm[];
    const int OAh = 0, OAl = 5120, OBh = 10240, OBl = 12800, BUFE = 15360; // elem offsets

    int tid = threadIdx.x, lane = tid & 31, wid = tid >> 5;
    int wm = wid >> 1, wn = wid & 1;
    long m0 = (long)blockIdx.y * 128;
    int  n0 = blockIdx.x * 64;

    const int NCH = KPAD / 32;

    auto stage = [&](int ch, int buf) {
        int k0 = ch * 32;
        __nv_bfloat16* base = dsm + buf * BUFE;
        #pragma unroll
        for (int i = 0; i < 4; i++) {
            int idx = tid + i * 128;
            int r = idx >> 2, g = idx & 3;
            cp16(smem_u32(base + OAh + r * 40 + g * 8), Ah + (m0 + r) * KPAD + k0 + g * 8);
            cp16(smem_u32(base + OAl + r * 40 + g * 8), Al + (m0 + r) * KPAD + k0 + g * 8);
        }
        #pragma unroll
        for (int i = 0; i < 2; i++) {
            int idx = tid + i * 128;
            int r = idx >> 2, g = idx & 3;
            cp16(smem_u32(base + OBh + r * 40 + g * 8), Wh + (long)(n0 + r) * KPAD + k0 + g * 8);
            cp16(smem_u32(base + OBl + r * 40 + g * 8), Wl + (long)(n0 + r) * KPAD + k0 + g * 8);
        }
        cp_commit();
    };

    float acc[4][4][4];
    #pragma unroll
    for (int i = 0; i < 4; i++)
        #pragma unroll
        for (int j = 0; j < 4; j++)
            #pragma unroll
            for (int q = 0; q < 4; q++) acc[i][j][q] = 0.0f;

    stage(0, 0);
    for (int ch = 0; ch < NCH; ch++) {
        int buf = ch & 1;
        if (ch + 1 < NCH) { stage(ch + 1, buf ^ 1); cp_wait<1>(); }
        else              { cp_wait<0>(); }
        __syncthreads();

        uint32_t uAh = smem_u32(dsm + buf * BUFE + OAh);
        uint32_t uAl = smem_u32(dsm + buf * BUFE + OAl);
        uint32_t uBh = smem_u32(dsm + buf * BUFE + OBh);
        uint32_t uBl = smem_u32(dsm + buf * BUFE + OBl);

        #pragma unroll
        for (int ks = 0; ks < 32; ks += 16) {
            uint32_t ah[4][4], al[4][4], bh[4][2], bl[4][2];
            #pragma unroll
            for (int mi = 0; mi < 4; mi++) {
                uint32_t off = (uint32_t)(((wm * 64 + mi * 16 + (lane & 15)) * 40 +
                                           ks + ((lane >> 4) << 3)) * 2);
                ldm_x4(ah[mi], uAh + off);
                ldm_x4(al[mi], uAl + off);
            }
            #pragma unroll
            for (int p = 0; p < 2; p++) {
                uint32_t off = (uint32_t)(((wn * 32 + p * 16 + (lane & 7) + ((lane >> 4) << 3)) * 40 +
                                           ks + (((lane >> 3) & 1) << 3)) * 2);
                uint32_t r4[4];
                ldm_x4(r4, uBh + off);
                bh[p * 2][0] = r4[0]; bh[p * 2][1] = r4[1];
                bh[p * 2 + 1][0] = r4[2]; bh[p * 2 + 1][1] = r4[3];
                ldm_x4(r4, uBl + off);
                bl[p * 2][0] = r4[0]; bl[p * 2][1] = r4[1];
                bl[p * 2 + 1][0] = r4[2]; bl[p * 2 + 1][1] = r4[3];
            }
            #pragma unroll
            for (int mi = 0; mi < 4; mi++)
                #pragma unroll
                for (int ni = 0; ni < 4; ni++) {
                    mma_bf16(acc[mi][ni], ah[mi], bh[ni]);
                    mma_bf16(acc[mi][ni], ah[mi], bl[ni]);
                    mma_bf16(acc[mi][ni], al[mi], bh[ni]);
                }
        }
        __syncthreads();
    }

    // epilogue: write y split bf16, natural [b][s][n]
    #pragma unroll
    for (int mi = 0; mi < 4; mi++) {
        #pragma unroll
        for (int half = 0; half < 2; half++) {
            long row = m0 + wm * 64 + mi * 16 + (lane >> 2) + half * 8;
            long b = row / TT;
            int  s = (int)(row % TT);
            long base = (b * SP + s) * NP;
            #pragma unroll
            for (int ni = 0; ni < 4; ni++) {
                int n = n0 + wn * 32 + ni * 8 + (lane & 3) * 2;
                float v0 = acc[mi][ni][half * 2 + 0];
                float v1 = acc[mi][ni][half * 2 + 1];
                __nv_bfloat16 h0, l0, h1, l1;
                bsplit(v0, h0, l0); bsplit(v1, h1, l1);
                *(uint32_t*)&Yh[base + n] = bpack(h0, h1);
                *(uint32_t*)&Yl[base + n] = bpack(l0, l1);
            }
        }
    }
}

// ---------------- adjacency GEMM: D = (A+I) @ y, cp.async double-buffered ----------------
__global__ __launch_bounds__(128)
void k_adj(const __nv_bfloat16* __restrict__ Yh, const __nv_bfloat16* __restrict__ Yl,
           const float* __restrict__ cvec, const float* __restrict__ bias,
           __nv_bfloat16* __restrict__ Hh, __nv_bfloat16* __restrict__ Hl,
           float* __restrict__ outp, int layer0) {
    __shared__ __nv_bfloat16 sA[2][128 * 40];
    __shared__ __nv_bfloat16 sYh[2][32 * 72], sYl[2][32 * 72];

    int tid = threadIdx.x, lane = tid & 31, wid = tid >> 5;
    int wm = wid >> 1, wn = wid & 1;
    int b  = blockIdx.z;
    int m0 = blockIdx.y * 72;       // 0 or 72 (tiles overlap; identical values)
    int n0 = blockIdx.x * 64;

    auto stage = [&](int ch, int buf) {
        int k0 = ch * 32;
        #pragma unroll
        for (int i = 0; i < 4; i++) {
            int idx = tid + i * 128;
            int r = idx >> 2, g = idx & 3;
            cp16(smem_u32(&sA[buf][r * 40 + g * 8]),
                 &g_ab[((long)b * TT + m0 + r) * SP + k0 + g * 8]);
        }
        #pragma unroll
        for (int i = 0; i < 2; i++) {
            int idx = tid + i * 128;
            int r = idx >> 3, g = idx & 7;
            long gb = ((long)b * SP + k0 + r) * NP + n0 + g * 8;
            cp16(smem_u32(&sYh[buf][r * 72 + g * 8]), &Yh[gb]);
            cp16(smem_u32(&sYl[buf][r * 72 + g * 8]), &Yl[gb]);
        }
        cp_commit();
    };

    float acc[4][4][4];
    #pragma unroll
    for (int i = 0; i < 4; i++)
        #pragma unroll
        for (int j = 0; j < 4; j++)
            #pragma unroll
            for (int q = 0; q < 4; q++) acc[i][j][q] = 0.0f;

    const int NCH = SP / 32;   // 7
    stage(0, 0);
    for (int ch = 0; ch < NCH; ch++) {
        int buf = ch & 1;
        if (ch + 1 < NCH) { stage(ch + 1, buf ^ 1); cp_wait<1>(); }
        else              { cp_wait<0>(); }
        __syncthreads();

        uint32_t uA  = smem_u32(sA[buf]);
        uint32_t uYh = smem_u32(sYh[buf]);
        uint32_t uYl = smem_u32(sYl[buf]);

        #pragma unroll
        for (int ks = 0; ks < 32; ks += 16) {
            uint32_t aa[4][4], bh[4][2], bl[4][2];
            #pragma unroll
            for (int mi = 0; mi < 4; mi++) {
                uint32_t off = (uint32_t)(((wm * 64 + mi * 16 + (lane & 15)) * 40 +
                                           ks + ((lane >> 4) << 3)) * 2);
                ldm_x4(aa[mi], uA + off);
            }
            #pragma unroll
            for (int p = 0; p < 2; p++) {
                uint32_t off = (uint32_t)(((ks + (lane & 15)) * 72 +
                                           wn * 32 + p * 16 + ((lane >> 4) << 3)) * 2);
                uint32_t r4[4];
                ldm_x4t(r4, uYh + off);
                bh[p * 2][0] = r4[0]; bh[p * 2][1] = r4[1];
                bh[p * 2 + 1][0] = r4[2]; bh[p * 2 + 1][1] = r4[3];
                ldm_x4t(r4, uYl + off);
                bl[p * 2][0] = r4[0]; bl[p * 2][1] = r4[1];
                bl[p * 2 + 1][0] = r4[2]; bl[p * 2 + 1][1] = r4[3];
            }
            #pragma unroll
            for (int mi = 0; mi < 4; mi++)
                #pragma unroll
                for (int ni = 0; ni < 4; ni++) {
                    mma_bf16(acc[mi][ni], aa[mi], bh[ni]);
                    mma_bf16(acc[mi][ni], aa[mi], bl[ni]);
                }
        }
        __syncthreads();
    }

    // fused epilogue
    #pragma unroll
    for (int mi = 0; mi < 4; mi++) {
        #pragma unroll
        for (int half = 0; half < 2; half++) {
            int t = m0 + wm * 64 + mi * 16 + (lane >> 2) + half * 8;   // < 200
            long bt = (long)b * TT + t;
            float rd = g_rd[bt];
            #pragma unroll
            for (int ni = 0; ni < 4; ni++) {
                int n = n0 + wn * 32 + ni * 8 + (lane & 3) * 2;
                if (n >= MEM) continue;
                float a0, a1;
                if (layer0) { a0 = cvec[bt * MEM + n]; a1 = cvec[bt * MEM + n + 1]; }
                else        { a0 = 2.0f * bias[n];     a1 = 2.0f * bias[n + 1]; }
                float v0 = (acc[mi][ni][half * 2 + 0] + a0) * rd;
                float v1 = (acc[mi][ni][half * 2 + 1] + a1) * rd;
                v0 = v0 > 0.0f ? v0 : 0.0f;
                v1 = v1 > 0.0f ? v1 : 0.0f;
                if (layer0) {
                    __nv_bfloat16 h0, l0, h1, l1;
                    bsplit(v0, h0, l0); bsplit(v1, h1, l1);
                    *(uint32_t*)&Hh[bt * KP1 + n] = bpack(h0, h1);
                    *(uint32_t*)&Hl[bt * KP1 + n] = bpack(l0, l1);
                } else {
                    *(float2*)&outp[bt * MEM + n] = make_float2(v0, v1);
                }
            }
        }
    }
}

// ---------------- launch ----------------
extern "C" void kernel_launch(void* const* d_in, const int* in_sizes, int n_in,
                              void* d_out, int out_size) {
    const int*   adj      = (const int*)d_in[0];
    const int*   words    = (const int*)d_in[1];
    const int*   pos      = (const int*)d_in[2];
    const int*   ner      = (const int*)d_in[3];
    const int*   dep_ids  = (const int*)d_in[4];
    const int*   dep_mask = (const int*)d_in[5];
    const float* wemb = (const float*)d_in[7];
    const float* pemb = (const float*)d_in[8];
    const float* nemb = (const float*)d_in[9];
    const float* demb = (const float*)d_in[10];
    const float* W0w  = (const float*)d_in[11];
    const float* W0b  = (const float*)d_in[12];
    const float* W1w  = (const float*)d_in[13];
    const float* W1b  = (const float*)d_in[14];
    float* out = (float*)d_out;

    const int SMEM_DENSE = 2 * 15360 * 2;   // 61440 bytes
    cudaFuncSetAttribute(k_dense<KP0>, cudaFuncAttributeMaxDynamicSharedMemorySize, SMEM_DENSE);
    cudaFuncSetAttribute(k_dense<KP1>, cudaFuncAttributeMaxDynamicSharedMemorySize, SMEM_DENSE);

    __nv_bfloat16 *xh, *xl, *hh, *hl, *yh, *yl, *zh, *zl, *w0h, *w0l, *w1h, *w1l;
    float* pc;
    cudaGetSymbolAddress((void**)&xh,  g_xh);  cudaGetSymbolAddress((void**)&xl,  g_xl);
    cudaGetSymbolAddress((void**)&hh,  g_hh);  cudaGetSymbolAddress((void**)&hl,  g_hl);
    cudaGetSymbolAddress((void**)&yh,  g_yh);  cudaGetSymbolAddress((void**)&yl,  g_yl);
    cudaGetSymbolAddress((void**)&zh,  g_zh);  cudaGetSymbolAddress((void**)&zl,  g_zl);
    cudaGetSymbolAddress((void**)&w0h, g_w0h); cudaGetSymbolAddress((void**)&w0l, g_w0l);
    cudaGetSymbolAddress((void**)&w1h, g_w1h); cudaGetSymbolAddress((void**)&w1l, g_w1l);
    cudaGetSymbolAddress((void**)&pc,  g_c);

    int write_mask = (out_size >= (int)(BT * MEM + BT));

    // prep
    k_wsplit<<<(NP * KP0 + 255) / 256, 256>>>(W0w, W1w);
    k_prep<<<BATCH, 256>>>(adj, out, write_mask);
    k_adjconv<<<(int)((long)BATCH * TT * (TT / 4) / 256), 256>>>(adj);
    k_gw<<<(int)((BT * 75 + 255) / 256), 256>>>(words, wemb);
    k_gpn<<<(int)(BT / 8), 256>>>(pos, ner, dep_ids, dep_mask, pemb, nemb, demb);
    {
        dim3 gc(NP / 64, (int)(BT / 128));
        k_densec<<<gc, 128>>>(W0b);
    }

    dim3 gd(NP / 64, (int)(BT / 128));         // (5, 400)
    dim3 ga(NP / 64, 3, BATCH);                // (5, 3, 256) -- y=3 covers 0,72,144 (wait) -- see below

    // NOTE: adjacency m-tiles: blockIdx.y * 72 must cover rows [0,200): y in {0,1}
    // (tile 0: rows 0..127, tile 1: rows 72..199). Keep y=2 as in R6.
    dim3 ga2(NP / 64, 2, BATCH);

    // layer 0
    k_dense<KP0><<<gd, 128, SMEM_DENSE>>>(xh, xl, w0h, w0l, yh, yl);
    k_adj<<<ga2, 128>>>(yh, yl, pc, nullptr, hh, hl, nullptr, 1);

    // layer 1
    k_dense<KP1><<<gd, 128, SMEM_DENSE>>>(hh, hl, w1h, w1l, zh, zl);
    k_adj<<<ga2, 128>>>(zh, zl, nullptr, W1b, nullptr, nullptr, out, 0);
}